// round 17
// baseline (speedup 1.0000x reference)
#include <cuda_runtime.h>

#define SEQ 100
#define NF  18
#define HD  16
#define BPW 8        // batches per CTA (one warp-pair)
#define WIN 4        // timesteps per sync window
#define NWIN (SEQ / WIN)   // 25

typedef unsigned long long u64;

// lane layout: lane = gp*16 + j; gp=0 -> (i,f) gates, gp=1 -> (g,o) gates
// i,f,o weights/biases PRE-SCALED by 0.5: sigmoid(x) = 0.5 + 0.5*tanh(half_pre)
struct __align__(16) Smem {
    float2 w1[NF + HD][32];   // prep staging: [row][lane] gate-pair
    float2 w2[2 * HD][32];    // rows 0..15: Wih2, 16..31: Whh2
    float2 bia1[32];
    float2 bia2[32];
    float  xs [WIN][NF * BPW];  // one window of x, batch-packed rows (32B each)
    float  h1d[HD][BPW];        // layer-1 recurrence (warp A private)
    float  h1r[8][HD][BPW];     // relu(h1) handoff, 8 slots = 2 window halves
    float  h2d[HD][BPW];        // layer-2 recurrence (warp B private)
};

__device__ __forceinline__ u64 ffma2(u64 a, u64 b, u64 c) {
    u64 d;
    asm("fma.rn.f32x2 %0, %1, %2, %3;" : "=l"(d) : "l"(a), "l"(b), "l"(c));
    return d;
}
__device__ __forceinline__ u64 dup2(float v) {
    u64 d;
    asm("mov.b64 %0, {%1, %1};" : "=l"(d) : "f"(v));
    return d;
}
__device__ __forceinline__ float2 unpk(u64 v) {
    float2 r;
    asm("mov.b64 {%0, %1}, %2;" : "=f"(r.x), "=f"(r.y) : "l"(v));
    return r;
}
// MUFU.TANH (sm_75+)
__device__ __forceinline__ float tanha(float x) {
    float r;
    asm("tanh.approx.f32 %0, %1;" : "=f"(r) : "f"(x));
    return r;
}
// sigmoid from HALF pre-activation (weights pre-scaled by 0.5)
__device__ __forceinline__ float sig_h(float half_pre) {
    return fmaf(tanha(half_pre), 0.5f, 0.5f);
}
__device__ __forceinline__ void ctabar() {
    asm volatile("bar.sync 0, 64;" ::: "memory");
}

// one k-row with REGISTER weight pair: 2 dup2, 2 broadcast LDS.128, 8 FFMA2
#define KSTEPW(W, OPPTR) do {                                            \
    u64 _wp = dup2((W).x), _wq = dup2((W).y);                            \
    ulonglong2 _oa = *(const ulonglong2*)(OPPTR);                        \
    ulonglong2 _ob = *(const ulonglong2*)((const float*)(OPPTR) + 4);    \
    P0 = ffma2(_oa.x, _wp, P0);  Q0 = ffma2(_oa.x, _wq, Q0);             \
    P1 = ffma2(_oa.y, _wp, P1);  Q1 = ffma2(_oa.y, _wq, Q1);             \
    P2 = ffma2(_ob.x, _wp, P2);  Q2 = ffma2(_ob.x, _wq, Q2);             \
    P3 = ffma2(_ob.y, _wp, P3);  Q3 = ffma2(_ob.y, _wq, Q3);             \
} while (0)

// gate exchange across halves + LSTM cell for this lane's 4 batches
#define CELL(CARR, HOUT) do {                                            \
    u64 t0 = __shfl_xor_sync(0xffffffffu, gp ? P0 : P2, 16);             \
    u64 t1 = __shfl_xor_sync(0xffffffffu, gp ? P1 : P3, 16);             \
    u64 t2 = __shfl_xor_sync(0xffffffffu, gp ? Q0 : Q2, 16);             \
    u64 t3 = __shfl_xor_sync(0xffffffffu, gp ? Q1 : Q3, 16);             \
    u64 iA = gp ? t0 : P0,  iB = gp ? t1 : P1;                           \
    u64 fA = gp ? t2 : Q0,  fB = gp ? t3 : Q1;                           \
    u64 gA = gp ? P2 : t0,  gB = gp ? P3 : t1;                           \
    u64 oA = gp ? Q2 : t2,  oB = gp ? Q3 : t3;                           \
    float2 vi0 = unpk(iA), vi1 = unpk(iB);                               \
    float2 vf0 = unpk(fA), vf1 = unpk(fB);                               \
    float2 vg0 = unpk(gA), vg1 = unpk(gB);                               \
    float2 vo0 = unpk(oA), vo1 = unpk(oB);                               \
    float iv[4] = {vi0.x, vi0.y, vi1.x, vi1.y};                          \
    float fv[4] = {vf0.x, vf0.y, vf1.x, vf1.y};                          \
    float gv[4] = {vg0.x, vg0.y, vg1.x, vg1.y};                          \
    float ov[4] = {vo0.x, vo0.y, vo1.x, vo1.y};                          \
    _Pragma("unroll")                                                    \
    for (int p = 0; p < 4; p++) {                                        \
        float ig = sig_h(iv[p]), fg = sig_h(fv[p]);                      \
        float gg = tanha(gv[p]), og = sig_h(ov[p]);                      \
        float c = fmaf(fg, (CARR)[p], ig * gg);                          \
        (CARR)[p] = c;                                                   \
        (HOUT)[p] = og * tanha(c);                                       \
    }                                                                    \
} while (0)

// 576 floats per window / 32 lanes = 18 per lane
#define XREGS 18

__global__ void __launch_bounds__(64, 7)
lstm2_kernel(const float* __restrict__ x,
             const float* __restrict__ Wih1, const float* __restrict__ Whh1,
             const float* __restrict__ bih1, const float* __restrict__ bhh1,
             const float* __restrict__ Wih2, const float* __restrict__ Whh2,
             const float* __restrict__ bih2, const float* __restrict__ bhh2,
             float* __restrict__ out)
{
    extern __shared__ Smem sm[];
    Smem& s = sm[0];
    const int tid = threadIdx.x;

    // ---- one-time weight prep into smem tables (i/f/o scaled by 0.5) ----
    for (int i = tid; i < (NF + HD) * 32; i += 64) {
        int row = i >> 5, l = i & 31;
        int jj = l & 15, gpp = l >> 4;
        int g0 = gpp * 32 + jj, g1 = gpp * 32 + 16 + jj;
        float s0 = gpp ? 1.0f : 0.5f;
        float2 w;
        if (row < NF) {
            int k = row;
            w = make_float2(Wih1[g0 * NF + k] * s0, Wih1[g1 * NF + k] * 0.5f);
        } else {
            int k = row - NF;
            w = make_float2(Whh1[g0 * HD + k] * s0, Whh1[g1 * HD + k] * 0.5f);
        }
        s.w1[row][l] = w;
    }
    for (int i = tid; i < 2 * HD * 32; i += 64) {
        int row = i >> 5, l = i & 31;
        int jj = l & 15, gpp = l >> 4;
        int g0 = gpp * 32 + jj, g1 = gpp * 32 + 16 + jj;
        float s0 = gpp ? 1.0f : 0.5f;
        float2 w;
        if (row < HD) {
            int k = row;
            w = make_float2(Wih2[g0 * HD + k] * s0, Wih2[g1 * HD + k] * 0.5f);
        } else {
            int k = row - HD;
            w = make_float2(Whh2[g0 * HD + k] * s0, Whh2[g1 * HD + k] * 0.5f);
        }
        s.w2[row][l] = w;
    }
    if (tid < 32) {
        int l = tid, jj = l & 15, gpp = l >> 4;
        int g0 = gpp * 32 + jj, g1 = gpp * 32 + 16 + jj;
        float s0 = gpp ? 1.0f : 0.5f;
        s.bia1[l] = make_float2((bih1[g0] + bhh1[g0]) * s0, (bih1[g1] + bhh1[g1]) * 0.5f);
        s.bia2[l] = make_float2((bih2[g0] + bhh2[g0]) * s0, (bih2[g1] + bhh2[g1]) * 0.5f);
    }
    __syncthreads();

    const int wA   = (tid < 32);
    const int lane = tid & 31;
    const int gp   = lane >> 4;
    const int j    = lane & 15;
    const int myb  = gp * 4;
    const long ctaBatch = (long)blockIdx.x * BPW;

    if (wA) {
        // =========================== WARP A: layer 1 ===========================
        const float* xbase = x + ctaBatch * (long)(SEQ * NF);

        float2 w1r[NF + HD];
#pragma unroll
        for (int r = 0; r < NF + HD; r++) w1r[r] = s.w1[r][lane];
        float2 bb = s.bia1[lane];
        const u64 BP = dup2(bb.x), BQ = dup2(bb.y);

        // zero h1 state
        *(float4*)&s.h1d[j][myb] = make_float4(0.f, 0.f, 0.f, 0.f);

        float c1[4] = {0.f, 0.f, 0.f, 0.f};
        float h1v[4];
        float xreg[XREGS];

        // prologue: stage window 0's x
#pragma unroll
        for (int i = 0; i < XREGS; i++) {
            int idx = lane + i * 32;
            int tc = idx / (NF * BPW), rem = idx % (NF * BPW);
            int k = rem >> 3, b = rem & 7;
            xreg[i] = xbase[(long)b * (SEQ * NF) + tc * NF + k];
        }
#pragma unroll
        for (int i = 0; i < XREGS; i++) {
            int idx = lane + i * 32;
            int tc = idx / (NF * BPW), rem = idx % (NF * BPW);
            s.xs[tc][rem] = xreg[i];
        }
        __syncwarp();

        for (int w = 0; w < NWIN; w++) {
            // prefetch next window's x into registers (latency hidden by window)
            if (w + 1 < NWIN) {
#pragma unroll
                for (int i = 0; i < XREGS; i++) {
                    int idx = lane + i * 32;
                    int tc = idx / (NF * BPW), rem = idx % (NF * BPW);
                    int k = rem >> 3, b = rem & 7;
                    xreg[i] = xbase[(long)b * (SEQ * NF) + ((w + 1) * WIN + tc) * NF + k];
                }
            }

#pragma unroll
            for (int tt = 0; tt < WIN; tt++) {
                const int t = w * WIN + tt;
                u64 P0 = BP, P1 = BP, P2 = BP, P3 = BP;
                u64 Q0 = BQ, Q1 = BQ, Q2 = BQ, Q3 = BQ;
                const float* xr = &s.xs[tt][0];
#pragma unroll
                for (int k = 0; k < NF; k++)
                    KSTEPW(w1r[k], xr + k * BPW);
#pragma unroll
                for (int k = 0; k < HD; k++)
                    KSTEPW(w1r[NF + k], &s.h1d[k][0]);

                CELL(c1, h1v);

                __syncwarp();   // all A lanes done reading old h1d
                *(float4*)&s.h1d[j][myb] =
                    make_float4(h1v[0], h1v[1], h1v[2], h1v[3]);
                *(float4*)&s.h1r[t & 7][j][myb] =
                    make_float4(fmaxf(h1v[0], 0.f), fmaxf(h1v[1], 0.f),
                                fmaxf(h1v[2], 0.f), fmaxf(h1v[3], 0.f));
                __syncwarp();   // new h1d visible to A's next step
            }

            // commit prefetched x (all of window w's xs reads are done)
            if (w + 1 < NWIN) {
#pragma unroll
                for (int i = 0; i < XREGS; i++) {
                    int idx = lane + i * 32;
                    int tc = idx / (NF * BPW), rem = idx % (NF * BPW);
                    s.xs[tc][rem] = xreg[i];
                }
                __syncwarp();
            }
            ctabar();   // publish window w's h1r to warp B
        }
    } else {
        // =========================== WARP B: layer 2 ===========================
        float2 w2r[2 * HD];
#pragma unroll
        for (int r = 0; r < 2 * HD; r++) w2r[r] = s.w2[r][lane];
        float2 bb = s.bia2[lane];
        const u64 BP2 = dup2(bb.x), BQ2 = dup2(bb.y);

        // zero h2 state
        *(float4*)&s.h2d[j][myb] = make_float4(0.f, 0.f, 0.f, 0.f);
        __syncwarp();

        float c2[4] = {0.f, 0.f, 0.f, 0.f};
        float h2v[4] = {0.f, 0.f, 0.f, 0.f};

        for (int w = 0; w < NWIN; w++) {
            ctabar();   // wait for window w's h1r from warp A
#pragma unroll
            for (int tt = 0; tt < WIN; tt++) {
                const int t = w * WIN + tt;
                u64 P0 = BP2, P1 = BP2, P2 = BP2, P3 = BP2;
                u64 Q0 = BQ2, Q1 = BQ2, Q2 = BQ2, Q3 = BQ2;
                // recurrent part first (matches R14/R16 accumulation order)
#pragma unroll
                for (int k = 0; k < HD; k++)
                    KSTEPW(w2r[HD + k], &s.h2d[k][0]);
                const float* hr = &s.h1r[t & 7][0][0];
#pragma unroll
                for (int k = 0; k < HD; k++)
                    KSTEPW(w2r[k], hr + k * BPW);

                CELL(c2, h2v);

                __syncwarp();   // all B lanes done reading old h2d
                *(float4*)&s.h2d[j][myb] =
                    make_float4(h2v[0], h2v[1], h2v[2], h2v[3]);
                __syncwarp();   // new h2d visible to B's next step
            }
        }

        // ---- output: relu(h2_last), [B, 16] ----
#pragma unroll
        for (int p = 0; p < 4; p++) {
            out[(ctaBatch + myb + p) * HD + j] = fmaxf(h2v[p], 0.f);
        }
    }
}

extern "C" void kernel_launch(void* const* d_in, const int* in_sizes, int n_in,
                              void* d_out, int out_size)
{
    const float* x    = (const float*)d_in[0];
    const float* Wih1 = (const float*)d_in[1];
    const float* Whh1 = (const float*)d_in[2];
    const float* bih1 = (const float*)d_in[3];
    const float* bhh1 = (const float*)d_in[4];
    const float* Wih2 = (const float*)d_in[5];
    const float* Whh2 = (const float*)d_in[6];
    const float* bih2 = (const float*)d_in[7];
    const float* bhh2 = (const float*)d_in[8];
    float* out = (float*)d_out;

    const int smem = (int)sizeof(Smem);   // ~24 KB
    cudaFuncSetAttribute(lstm2_kernel,
                         cudaFuncAttributeMaxDynamicSharedMemorySize, smem);

    // 16384 batch / 8 per CTA = 2048 CTAs of 64 threads (warp A + warp B)
    lstm2_kernel<<<2048, 64, smem>>>(x, Wih1, Whh1, bih1, bhh1,
                                     Wih2, Whh2, bih2, bhh2, out);
}